// round 1
// baseline (speedup 1.0000x reference)
#include <cuda_runtime.h>
#include <cstdint>

#define N_NODES 100000
#define N_EDGES 3200000
#define D       256

// Scratch (no cudaMalloc allowed): y = x @ W^T, and transposed weights.
__device__ float g_y[(size_t)N_NODES * D];   // ~102.4 MB
__device__ float g_Wt[D * D];                // Wt[k][n] = W[n][k]

// ---------------------------------------------------------------------------
// Kernel 0: transpose W (tiny, 256 KB) so the GEMM B-operand loads coalesced.
// ---------------------------------------------------------------------------
__global__ void transpose_W_kernel(const float* __restrict__ W) {
    int n = threadIdx.x;   // 0..255
    int k = blockIdx.x;    // 0..255
    g_Wt[k * D + n] = W[n * D + k];
}

// ---------------------------------------------------------------------------
// Kernel 1: y = x @ W^T   (y[m][n] = sum_k x[m][k] * Wt[k][n])
// Classic SIMT tiled fp32 GEMM: BM=64, BN=64, BK=16, 256 threads, 4x4/thread.
// ---------------------------------------------------------------------------
__global__ __launch_bounds__(256) void gemm_xWt_kernel(const float* __restrict__ x) {
    const int BM = 64, BN = 64, BK = 16;
    __shared__ float As[BM][BK];     // x tile
    __shared__ float Bs[BK][BN];     // Wt tile

    int tid = threadIdx.x;
    int tx = tid & 15;       // 0..15  -> 4 output cols
    int ty = tid >> 4;       // 0..15  -> 4 output rows
    int m0 = blockIdx.y * BM;
    int n0 = blockIdx.x * BN;

    float acc[4][4] = {};

    for (int k0 = 0; k0 < D; k0 += BK) {
        // Load As: 64x16 floats = 256 float4, one per thread.
        {
            int r  = tid >> 2;          // 0..63
            int kv = tid & 3;           // 0..3 (float4 within 16)
            int gm = m0 + r;
            float4 v = make_float4(0.f, 0.f, 0.f, 0.f);
            if (gm < N_NODES)
                v = *(const float4*)(x + (size_t)gm * D + k0 + kv * 4);
            *(float4*)&As[r][kv * 4] = v;
        }
        // Load Bs: 16x64 floats = 256 float4, one per thread.
        {
            int kr = tid >> 4;          // 0..15
            int nv = tid & 15;          // 0..15
            float4 v = *(const float4*)(g_Wt + (size_t)(k0 + kr) * D + n0 + nv * 4);
            *(float4*)&Bs[kr][nv * 4] = v;
        }
        __syncthreads();

        #pragma unroll
        for (int kk = 0; kk < BK; kk++) {
            float a[4];
            #pragma unroll
            for (int i = 0; i < 4; i++) a[i] = As[ty * 4 + i][kk];
            float4 b4 = *(float4*)&Bs[kk][tx * 4];
            float b[4] = {b4.x, b4.y, b4.z, b4.w};
            #pragma unroll
            for (int i = 0; i < 4; i++)
                #pragma unroll
                for (int j = 0; j < 4; j++)
                    acc[i][j] = fmaf(a[i], b[j], acc[i][j]);
        }
        __syncthreads();
    }

    #pragma unroll
    for (int i = 0; i < 4; i++) {
        int gm = m0 + ty * 4 + i;
        if (gm < N_NODES) {
            float4 v = make_float4(acc[i][0], acc[i][1], acc[i][2], acc[i][3]);
            *(float4*)(g_y + (size_t)gm * D + n0 + tx * 4) = v;
        }
    }
}

// ---------------------------------------------------------------------------
// Kernel 2: scatter  out[row_e] += val_e * y[col_e]   (one warp per edge)
// Each lane handles 8 columns as two float4 loads + two red.global.add.v4.f32.
// ---------------------------------------------------------------------------
__global__ __launch_bounds__(256) void scatter_edges_kernel(
    const int*   __restrict__ erow,
    const int*   __restrict__ ecol,
    const float* __restrict__ eval,
    float*       __restrict__ out)
{
    int e = (int)((blockIdx.x * (unsigned)blockDim.x + threadIdx.x) >> 5);
    if (e >= N_EDGES) return;
    int lane = threadIdx.x & 31;

    int   r = __ldg(erow + e);
    int   c = __ldg(ecol + e);
    float v = __ldg(eval + e);

    const float4* src = (const float4*)(g_y + (size_t)c * D);
    float4*       dst = (float4*)(out + (size_t)r * D);

    #pragma unroll
    for (int i = 0; i < 2; i++) {
        float4 m = __ldg(src + lane + i * 32);
        m.x *= v; m.y *= v; m.z *= v; m.w *= v;
        asm volatile(
            "red.global.add.v4.f32 [%0], {%1, %2, %3, %4};"
            :: "l"(dst + lane + i * 32), "f"(m.x), "f"(m.y), "f"(m.z), "f"(m.w)
            : "memory");
    }
}

// ---------------------------------------------------------------------------
// Launch
// ---------------------------------------------------------------------------
extern "C" void kernel_launch(void* const* d_in, const int* in_sizes, int n_in,
                              void* d_out, int out_size) {
    const float* x    = (const float*)d_in[0];
    const int*   erow = (const int*)  d_in[1];
    const int*   ecol = (const int*)  d_in[2];
    const float* eval = (const float*)d_in[3];
    const float* W    = (const float*)d_in[4];
    float*       out  = (float*)d_out;

    // d_out is poisoned; zero it for the atomic accumulation.
    cudaMemsetAsync(out, 0, (size_t)N_NODES * D * sizeof(float));

    transpose_W_kernel<<<D, D>>>(W);

    dim3 ggrid(D / 64, (N_NODES + 63) / 64);   // (4, 1563)
    gemm_xWt_kernel<<<ggrid, 256>>>(x);

    int warps  = N_EDGES;                       // one warp per edge
    int blocks = (warps * 32 + 255) / 256;      // 400000 blocks
    scatter_edges_kernel<<<blocks, 256>>>(erow, ecol, eval, out);
}

// round 2
// speedup vs baseline: 1.8345x; 1.8345x over previous
#include <cuda_runtime.h>
#include <cstdint>

#define N_NODES 100000
#define N_EDGES 3200000
#define D       256
#define SCAN_BS 1024
#define N_CHUNK ((N_NODES + SCAN_BS - 1) / SCAN_BS)   // 98

// ---------------- device scratch (no cudaMalloc allowed) ----------------
__device__ float g_y[(size_t)N_NODES * D];   // y = x @ W^T  (~102.4 MB)
__device__ float g_Wt[D * D];                // W transposed
__device__ int   g_cnt[N_NODES];             // per-row edge count
__device__ int   g_incl[N_NODES];            // inclusive scan within chunk
__device__ int   g_csum[N_CHUNK];            // chunk totals
__device__ int   g_coff[N_CHUNK];            // exclusive chunk offsets
__device__ int   g_start[N_NODES];           // CSR row start
__device__ int   g_end[N_NODES];             // CSR row end
__device__ int   g_cursor[N_NODES];          // scatter cursors
__device__ int2  g_edges[N_EDGES];           // row-sorted (col, val-bits)

// ---------------------------------------------------------------------------
// K0: transpose W + zero counts (fused; both tiny)
// ---------------------------------------------------------------------------
__global__ void prep_kernel(const float* __restrict__ W) {
    int n = threadIdx.x, k = blockIdx.x;
    g_Wt[k * D + n] = W[n * D + k];
    int i = k * D + n;                        // 0..65535, covers 100000 in 2 strides
    for (; i < N_NODES; i += D * D) g_cnt[i] = 0;
}

// ---------------------------------------------------------------------------
// K1: histogram of edge rows
// ---------------------------------------------------------------------------
__global__ __launch_bounds__(256) void hist_kernel(const int* __restrict__ erow) {
    int e = blockIdx.x * 256 + threadIdx.x;
    if (e < N_EDGES) atomicAdd(&g_cnt[erow[e]], 1);
}

// ---------------------------------------------------------------------------
// K2: per-chunk inclusive scan (1024 elems/chunk)
// ---------------------------------------------------------------------------
__device__ __forceinline__ int warp_incl_scan(int v, int lane) {
    #pragma unroll
    for (int d = 1; d < 32; d <<= 1) {
        int n = __shfl_up_sync(0xffffffffu, v, d);
        if (lane >= d) v += n;
    }
    return v;
}

__global__ __launch_bounds__(SCAN_BS) void scan1_kernel() {
    __shared__ int wsum[32];
    int tid = threadIdx.x, lane = tid & 31, wid = tid >> 5;
    int i = blockIdx.x * SCAN_BS + tid;
    int v = (i < N_NODES) ? g_cnt[i] : 0;
    int s = warp_incl_scan(v, lane);
    if (lane == 31) wsum[wid] = s;
    __syncthreads();
    if (wid == 0) {
        int w = wsum[lane];
        w = warp_incl_scan(w, lane);
        wsum[lane] = w;
    }
    __syncthreads();
    int off = (wid > 0) ? wsum[wid - 1] : 0;
    int incl = s + off;
    if (i < N_NODES) g_incl[i] = incl;
    if (tid == SCAN_BS - 1) g_csum[blockIdx.x] = incl;
}

// ---------------------------------------------------------------------------
// K3: scan the chunk totals (N_CHUNK <= 128) -> exclusive offsets
// ---------------------------------------------------------------------------
__global__ void scan2_kernel() {
    __shared__ int wsum[4];
    int tid = threadIdx.x, lane = tid & 31, wid = tid >> 5;   // 128 threads
    int v = (tid < N_CHUNK) ? g_csum[tid] : 0;
    int s = warp_incl_scan(v, lane);
    if (lane == 31) wsum[wid] = s;
    __syncthreads();
    if (tid < 4) {
        int w = wsum[tid];
        // serial scan of 4 values in lane 0..3 via shuffle
        #pragma unroll
        for (int d = 1; d < 4; d <<= 1) {
            int n = __shfl_up_sync(0x0000000fu, w, d);
            if (tid >= d) w += n;
        }
        wsum[tid] = w;
    }
    __syncthreads();
    int off = (wid > 0) ? wsum[wid - 1] : 0;
    if (tid < N_CHUNK) g_coff[tid] = s + off - v;   // exclusive
}

// ---------------------------------------------------------------------------
// K4: finalize row starts/ends + init cursors
// ---------------------------------------------------------------------------
__global__ __launch_bounds__(256) void scan3_kernel() {
    int i = blockIdx.x * 256 + threadIdx.x;
    if (i >= N_NODES) return;
    int incl = g_coff[i >> 10] + g_incl[i];
    int st   = incl - g_cnt[i];
    g_start[i]  = st;
    g_end[i]    = incl;
    g_cursor[i] = st;
}

// ---------------------------------------------------------------------------
// K5: permute edges into row-sorted order
// ---------------------------------------------------------------------------
__global__ __launch_bounds__(256) void build_kernel(
    const int* __restrict__ erow, const int* __restrict__ ecol,
    const float* __restrict__ eval)
{
    int e = blockIdx.x * 256 + threadIdx.x;
    if (e >= N_EDGES) return;
    int r = erow[e];
    int p = atomicAdd(&g_cursor[r], 1);
    g_edges[p] = make_int2(ecol[e], __float_as_int(eval[e]));
}

// ---------------------------------------------------------------------------
// K6: y = x @ W^T   (BM=64, BN=64, BK=16, 256 threads, 4x4/thread)
// ---------------------------------------------------------------------------
__global__ __launch_bounds__(256) void gemm_xWt_kernel(const float* __restrict__ x) {
    const int BM = 64, BN = 64, BK = 16;
    __shared__ float As[BM][BK];
    __shared__ float Bs[BK][BN];

    int tid = threadIdx.x;
    int tx = tid & 15, ty = tid >> 4;
    int m0 = blockIdx.y * BM, n0 = blockIdx.x * BN;

    float acc[4][4] = {};

    for (int k0 = 0; k0 < D; k0 += BK) {
        {
            int r = tid >> 2, kv = tid & 3;
            int gm = m0 + r;
            float4 v = make_float4(0.f, 0.f, 0.f, 0.f);
            if (gm < N_NODES)
                v = *(const float4*)(x + (size_t)gm * D + k0 + kv * 4);
            *(float4*)&As[r][kv * 4] = v;
        }
        {
            int kr = tid >> 4, nv = tid & 15;
            float4 v = *(const float4*)(g_Wt + (size_t)(k0 + kr) * D + n0 + nv * 4);
            *(float4*)&Bs[kr][nv * 4] = v;
        }
        __syncthreads();

        #pragma unroll
        for (int kk = 0; kk < BK; kk++) {
            float a[4];
            #pragma unroll
            for (int i = 0; i < 4; i++) a[i] = As[ty * 4 + i][kk];
            float4 b4 = *(float4*)&Bs[kk][tx * 4];
            float b[4] = {b4.x, b4.y, b4.z, b4.w};
            #pragma unroll
            for (int i = 0; i < 4; i++)
                #pragma unroll
                for (int j = 0; j < 4; j++)
                    acc[i][j] = fmaf(a[i], b[j], acc[i][j]);
        }
        __syncthreads();
    }

    #pragma unroll
    for (int i = 0; i < 4; i++) {
        int gm = m0 + ty * 4 + i;
        if (gm < N_NODES)
            *(float4*)(g_y + (size_t)gm * D + n0 + tx * 4) =
                make_float4(acc[i][0], acc[i][1], acc[i][2], acc[i][3]);
    }
}

// ---------------------------------------------------------------------------
// K7: atomic-free aggregation: out[i] = sum_{e in row i} val_e * y[col_e]
// One warp per node; each lane owns 8 output floats (two float4 slots).
// ---------------------------------------------------------------------------
__global__ __launch_bounds__(256) void agg_kernel(float* __restrict__ out) {
    int gw = (blockIdx.x * 256 + threadIdx.x) >> 5;    // global warp = node id
    if (gw >= N_NODES) return;
    int lane = threadIdx.x & 31;

    int s = g_start[gw];
    int e = g_end[gw];

    float4 a0 = make_float4(0.f, 0.f, 0.f, 0.f);
    float4 a1 = make_float4(0.f, 0.f, 0.f, 0.f);

    for (int base = s; base < e; base += 32) {
        int idx = base + lane;
        int2 ed = (idx < e) ? g_edges[idx] : make_int2(0, 0);
        int m = min(32, e - base);
        for (int j = 0; j < m; j++) {
            int   c = __shfl_sync(0xffffffffu, ed.x, j);
            float v = __int_as_float(__shfl_sync(0xffffffffu, ed.y, j));
            const float4* src = (const float4*)(g_y + (size_t)c * D);
            float4 m0 = __ldg(src + lane);
            float4 m1 = __ldg(src + lane + 32);
            a0.x = fmaf(v, m0.x, a0.x); a0.y = fmaf(v, m0.y, a0.y);
            a0.z = fmaf(v, m0.z, a0.z); a0.w = fmaf(v, m0.w, a0.w);
            a1.x = fmaf(v, m1.x, a1.x); a1.y = fmaf(v, m1.y, a1.y);
            a1.z = fmaf(v, m1.z, a1.z); a1.w = fmaf(v, m1.w, a1.w);
        }
    }

    float4* dst = (float4*)(out + (size_t)gw * D);
    dst[lane]      = a0;
    dst[lane + 32] = a1;
}

// ---------------------------------------------------------------------------
// Launch
// ---------------------------------------------------------------------------
extern "C" void kernel_launch(void* const* d_in, const int* in_sizes, int n_in,
                              void* d_out, int out_size) {
    const float* x    = (const float*)d_in[0];
    const int*   erow = (const int*)  d_in[1];
    const int*   ecol = (const int*)  d_in[2];
    const float* eval = (const float*)d_in[3];
    const float* W    = (const float*)d_in[4];
    float*       out  = (float*)d_out;

    const int EB = (N_EDGES + 255) / 256;      // 12500
    const int NB = (N_NODES + 255) / 256;      // 391

    prep_kernel<<<D, D>>>(W);
    hist_kernel<<<EB, 256>>>(erow);
    scan1_kernel<<<N_CHUNK, SCAN_BS>>>();
    scan2_kernel<<<1, 128>>>();
    scan3_kernel<<<NB, 256>>>();
    build_kernel<<<EB, 256>>>(erow, ecol, eval);

    dim3 ggrid(D / 64, (N_NODES + 63) / 64);
    gemm_xWt_kernel<<<ggrid, 256>>>(x);

    agg_kernel<<<(N_NODES * 32 + 255) / 256, 256>>>(out);
}

// round 16
// speedup vs baseline: 3.5969x; 1.9607x over previous
#include <cuda_runtime.h>
#include <cuda_fp16.h>
#include <cstdint>

#define N_NODES 100000
#define N_EDGES 3200000
#define D       256
#define SCAN_BS 1024
#define N_CHUNK ((N_NODES + SCAN_BS - 1) / SCAN_BS)   // 98

// ---------------- device scratch (no cudaMalloc allowed) ----------------
__device__ __half g_yh[(size_t)N_NODES * D];  // y = x @ W^T, fp16 (~51.2 MB)
__device__ int   g_cnt[N_NODES];
__device__ int   g_incl[N_NODES];
__device__ int   g_csum[N_CHUNK];
__device__ int   g_coff[N_CHUNK];
__device__ int   g_start[N_NODES];
__device__ int   g_end[N_NODES];
__device__ int   g_cursor[N_NODES];
__device__ int2  g_edges[N_EDGES];

// ---------------------------------------------------------------------------
// K0: zero counts
// ---------------------------------------------------------------------------
__global__ void zero_cnt_kernel() {
    int i = blockIdx.x * 256 + threadIdx.x;
    if (i < N_NODES) g_cnt[i] = 0;
}

// ---------------------------------------------------------------------------
// K1: histogram of edge rows
// ---------------------------------------------------------------------------
__global__ __launch_bounds__(256) void hist_kernel(const int* __restrict__ erow) {
    int e = blockIdx.x * 256 + threadIdx.x;
    if (e < N_EDGES) atomicAdd(&g_cnt[erow[e]], 1);
}

// ---------------------------------------------------------------------------
// K2-K4: scan
// ---------------------------------------------------------------------------
__device__ __forceinline__ int warp_incl_scan(int v, int lane) {
    #pragma unroll
    for (int d = 1; d < 32; d <<= 1) {
        int n = __shfl_up_sync(0xffffffffu, v, d);
        if (lane >= d) v += n;
    }
    return v;
}

__global__ __launch_bounds__(SCAN_BS) void scan1_kernel() {
    __shared__ int wsum[32];
    int tid = threadIdx.x, lane = tid & 31, wid = tid >> 5;
    int i = blockIdx.x * SCAN_BS + tid;
    int v = (i < N_NODES) ? g_cnt[i] : 0;
    int s = warp_incl_scan(v, lane);
    if (lane == 31) wsum[wid] = s;
    __syncthreads();
    if (wid == 0) wsum[lane] = warp_incl_scan(wsum[lane], lane);
    __syncthreads();
    int off = (wid > 0) ? wsum[wid - 1] : 0;
    int incl = s + off;
    if (i < N_NODES) g_incl[i] = incl;
    if (tid == SCAN_BS - 1) g_csum[blockIdx.x] = incl;
}

__global__ void scan2_kernel() {
    __shared__ int wsum[4];
    int tid = threadIdx.x, lane = tid & 31, wid = tid >> 5;
    int v = (tid < N_CHUNK) ? g_csum[tid] : 0;
    int s = warp_incl_scan(v, lane);
    if (lane == 31) wsum[wid] = s;
    __syncthreads();
    if (tid < 4) {
        int w = wsum[tid];
        #pragma unroll
        for (int d = 1; d < 4; d <<= 1) {
            int n = __shfl_up_sync(0x0000000fu, w, d);
            if (tid >= d) w += n;
        }
        wsum[tid] = w;
    }
    __syncthreads();
    int off = (wid > 0) ? wsum[wid - 1] : 0;
    if (tid < N_CHUNK) g_coff[tid] = s + off - v;
}

__global__ __launch_bounds__(256) void scan3_kernel() {
    int i = blockIdx.x * 256 + threadIdx.x;
    if (i >= N_NODES) return;
    int incl = g_coff[i >> 10] + g_incl[i];
    int st   = incl - g_cnt[i];
    g_start[i]  = st;
    g_end[i]    = incl;
    g_cursor[i] = st;
}

// ---------------------------------------------------------------------------
// K5: permute edges into row-sorted order
// ---------------------------------------------------------------------------
__global__ __launch_bounds__(256) void build_kernel(
    const int* __restrict__ erow, const int* __restrict__ ecol,
    const float* __restrict__ eval)
{
    int e = blockIdx.x * 256 + threadIdx.x;
    if (e >= N_EDGES) return;
    int r = erow[e];
    int p = atomicAdd(&g_cursor[r], 1);
    g_edges[p] = make_int2(ecol[e], __float_as_int(eval[e]));
}

// ---------------------------------------------------------------------------
// K6: y = x @ W^T via mma.sync tf32 (m16n8k8 HMMA path — compiles under the
// harness's compute_103 PTX stage; tcgen05 does not).
// CTA tile 128x128, BK=32, 256 threads = 8 warps in 4(m) x 2(n).
// Each warp: 32(m) x 64(n) = 2 x 8 m16n8 tiles, fp32 accumulate, fp16 store.
// ---------------------------------------------------------------------------
#define A_PITCH 36    // (g*4+tig) mod 32 distinct -> conflict-free A frag LDS
#define B_PITCH 136   // (tig*8+g) mod 32 distinct -> conflict-free B frag LDS

__device__ __forceinline__ uint32_t f2tf32(float f) {
    uint32_t u;
    asm("cvt.rna.tf32.f32 %0, %1;" : "=r"(u) : "f"(f));
    return u;
}

__global__ __launch_bounds__(256) void gemm_tf32_kernel(
    const float* __restrict__ x, const float* __restrict__ W)
{
    __shared__ uint32_t As[128 * A_PITCH];   // [m][k] tf32 bits
    __shared__ uint32_t Bs[32 * B_PITCH];    // [k][n] tf32 bits

    const int tid  = threadIdx.x;
    const int wid  = tid >> 5;
    const int lane = tid & 31;
    const int g    = lane >> 2;      // groupID 0..7
    const int tig  = lane & 3;       // threadID_in_group 0..3
    const int wm   = wid & 3;        // warp m index 0..3 -> rows wm*32
    const int wn   = wid >> 2;       // warp n index 0..1 -> cols wn*64
    const int m0   = blockIdx.y * 128;
    const int n0   = blockIdx.x * 128;

    float c[2][8][4];
    #pragma unroll
    for (int mt = 0; mt < 2; mt++)
        #pragma unroll
        for (int nt = 0; nt < 8; nt++)
            #pragma unroll
            for (int i = 0; i < 4; i++) c[mt][nt][i] = 0.f;

    for (int kt = 0; kt < D; kt += 32) {
        // ---- load A tile: x[m0..m0+127][kt..kt+31] -> As (tf32) ----
        #pragma unroll
        for (int p = 0; p < 4; p++) {
            int row = (tid >> 3) + p * 32;     // 0..127
            int c4  = (tid & 7) * 4;           // 0,4,..28
            float4 v = make_float4(0.f, 0.f, 0.f, 0.f);
            if (m0 + row < N_NODES)
                v = *(const float4*)(x + (size_t)(m0 + row) * D + kt + c4);
            uint32_t* dst = As + row * A_PITCH + c4;
            dst[0] = f2tf32(v.x); dst[1] = f2tf32(v.y);
            dst[2] = f2tf32(v.z); dst[3] = f2tf32(v.w);
        }
        // ---- load B tile: W[n0..n0+127][kt..kt+31] -> Bs[k][n] (tf32) ----
        #pragma unroll
        for (int p = 0; p < 4; p++) {
            int n  = (tid >> 3) + p * 32;      // 0..127
            int c4 = (tid & 7) * 4;
            float4 v = *(const float4*)(W + (size_t)(n0 + n) * D + kt + c4);
            Bs[(c4 + 0) * B_PITCH + n] = f2tf32(v.x);
            Bs[(c4 + 1) * B_PITCH + n] = f2tf32(v.y);
            Bs[(c4 + 2) * B_PITCH + n] = f2tf32(v.z);
            Bs[(c4 + 3) * B_PITCH + n] = f2tf32(v.w);
        }
        __syncthreads();

        // ---- compute: 4 k-steps of 8 ----
        #pragma unroll
        for (int ks = 0; ks < 4; ks++) {
            int kk = ks * 8;
            uint32_t a[2][4];
            #pragma unroll
            for (int mt = 0; mt < 2; mt++) {
                int mr = wm * 32 + mt * 16;
                const uint32_t* ap = As + (mr + g) * A_PITCH + kk + tig;
                a[mt][0] = ap[0];
                a[mt][1] = ap[8 * A_PITCH];
                a[mt][2] = ap[4];
                a[mt][3] = ap[8 * A_PITCH + 4];
            }
            #pragma unroll
            for (int nt = 0; nt < 8; nt++) {
                int nc = wn * 64 + nt * 8 + g;
                uint32_t b0 = Bs[(kk + tig) * B_PITCH + nc];
                uint32_t b1 = Bs[(kk + tig + 4) * B_PITCH + nc];
                #pragma unroll
                for (int mt = 0; mt < 2; mt++) {
                    asm volatile(
                        "mma.sync.aligned.m16n8k8.row.col.f32.tf32.tf32.f32 "
                        "{%0,%1,%2,%3}, {%4,%5,%6,%7}, {%8,%9}, {%0,%1,%2,%3};"
                        : "+f"(c[mt][nt][0]), "+f"(c[mt][nt][1]),
                          "+f"(c[mt][nt][2]), "+f"(c[mt][nt][3])
                        : "r"(a[mt][0]), "r"(a[mt][1]), "r"(a[mt][2]), "r"(a[mt][3]),
                          "r"(b0), "r"(b1));
                }
            }
        }
        __syncthreads();
    }

    // ---- epilogue: write C to g_yh as fp16 (c0,c1 / c2,c3 are adjacent cols)
    #pragma unroll
    for (int mt = 0; mt < 2; mt++) {
        int r_lo = m0 + wm * 32 + mt * 16 + g;
        int r_hi = r_lo + 8;
        #pragma unroll
        for (int nt = 0; nt < 8; nt++) {
            int col = n0 + wn * 64 + nt * 8 + 2 * tig;
            if (r_lo < N_NODES)
                *(__half2*)(g_yh + (size_t)r_lo * D + col) =
                    __floats2half2_rn(c[mt][nt][0], c[mt][nt][1]);
            if (r_hi < N_NODES)
                *(__half2*)(g_yh + (size_t)r_hi * D + col) =
                    __floats2half2_rn(c[mt][nt][2], c[mt][nt][3]);
        }
    }
}

// ---------------------------------------------------------------------------
// K7: atomic-free aggregation over fp16 y.
// One warp per node; lane owns 8 consecutive cols = one 16-B uint4 (4 half2).
// ---------------------------------------------------------------------------
__global__ __launch_bounds__(256) void agg_kernel(float* __restrict__ out) {
    int gw = (blockIdx.x * 256 + threadIdx.x) >> 5;
    if (gw >= N_NODES) return;
    int lane = threadIdx.x & 31;

    int s = g_start[gw];
    int e = g_end[gw];

    float a[8];
    #pragma unroll
    for (int q = 0; q < 8; q++) a[q] = 0.f;

    for (int base = s; base < e; base += 32) {
        int idx = base + lane;
        int2 ed = (idx < e) ? g_edges[idx] : make_int2(0, 0);
        int m = min(32, e - base);
        for (int j = 0; j < m; j++) {
            int   c = __shfl_sync(0xffffffffu, ed.x, j);
            float v = __int_as_float(__shfl_sync(0xffffffffu, ed.y, j));
            uint4 raw = __ldg((const uint4*)(g_yh + (size_t)c * D) + lane);
            const __half2* hp = (const __half2*)&raw;
            #pragma unroll
            for (int q = 0; q < 4; q++) {
                float2 f = __half22float2(hp[q]);
                a[q * 2 + 0] = fmaf(v, f.x, a[q * 2 + 0]);
                a[q * 2 + 1] = fmaf(v, f.y, a[q * 2 + 1]);
            }
        }
    }

    float* dst = out + (size_t)gw * D + lane * 8;
    *(float4*)(dst)     = make_float4(a[0], a[1], a[2], a[3]);
    *(float4*)(dst + 4) = make_float4(a[4], a[5], a[6], a[7]);
}

// ---------------------------------------------------------------------------
// Launch
// ---------------------------------------------------------------------------
extern "C" void kernel_launch(void* const* d_in, const int* in_sizes, int n_in,
                              void* d_out, int out_size) {
    const float* x    = (const float*)d_in[0];
    const int*   erow = (const int*)  d_in[1];
    const int*   ecol = (const int*)  d_in[2];
    const float* eval = (const float*)d_in[3];
    const float* W    = (const float*)d_in[4];
    float*       out  = (float*)d_out;

    const int EB = (N_EDGES + 255) / 256;
    const int NB = (N_NODES + 255) / 256;

    zero_cnt_kernel<<<NB, 256>>>();
    hist_kernel<<<EB, 256>>>(erow);
    scan1_kernel<<<N_CHUNK, SCAN_BS>>>();
    scan2_kernel<<<1, 128>>>();
    scan3_kernel<<<NB, 256>>>();
    build_kernel<<<EB, 256>>>(erow, ecol, eval);

    dim3 ggrid(D / 128, (N_NODES + 127) / 128);   // (2, 782)
    gemm_tf32_kernel<<<ggrid, 256>>>(x, W);

    agg_kernel<<<(N_NODES * 32 + 255) / 256, 256>>>(out);
}